// round 1
// baseline (speedup 1.0000x reference)
#include <cuda_runtime.h>

#define H 4
#define KCODES 8192
#define DFULL 1024
#define DHEAD 256
#define BATCH 8192

#define BM 128
#define BN 128
#define BK 8
#define TM 8
#define TN 8

// Scratch (no allocations allowed)
__device__ unsigned long long g_min[BATCH * H];
__device__ float g_e2[H * KCODES];

// ---------------------------------------------------------------------------
// Reset packed (dist,code) mins
// ---------------------------------------------------------------------------
__global__ void reset_kernel() {
    int i = blockIdx.x * blockDim.x + threadIdx.x;
    if (i < BATCH * H) g_min[i] = 0xFFFFFFFFFFFFFFFFull;
}

// ---------------------------------------------------------------------------
// e2[h,k] = sum_d codebooks[h,k,d]^2   (warp per code row)
// ---------------------------------------------------------------------------
__global__ void e2_kernel(const float* __restrict__ cb) {
    int warp = (blockIdx.x * blockDim.x + threadIdx.x) >> 5;
    int lane = threadIdx.x & 31;
    if (warp >= H * KCODES) return;
    const float* p = cb + (size_t)warp * DHEAD;
    float s = 0.f;
#pragma unroll
    for (int i = 0; i < DHEAD; i += 32) {
        float v = p[i + lane];
        s = fmaf(v, v, s);
    }
#pragma unroll
    for (int o = 16; o; o >>= 1) s += __shfl_xor_sync(0xFFFFFFFFu, s, o);
    if (lane == 0) g_e2[warp] = s;
}

// ---------------------------------------------------------------------------
// Fused GEMM (x . e^T) + argmin over k of (e2 - 2*xe).
// Block: 128 b-rows x 128 k-cols, 256 threads, 8x8 microtile, BK=8 k-depth.
// ---------------------------------------------------------------------------
__device__ __forceinline__ unsigned float_key(float f) {
    unsigned ub = __float_as_uint(f);
    return (ub & 0x80000000u) ? ~ub : (ub | 0x80000000u);
}

__global__ __launch_bounds__(256, 2)
void dist_argmin_kernel(const float* __restrict__ x, const float* __restrict__ cb) {
    __shared__ float Xs[BK][BM];
    __shared__ float Es[BK][BN];
    __shared__ unsigned long long red[BM][17];

    const int h  = blockIdx.z;
    const int bi = blockIdx.x * BM;
    const int kj = blockIdx.y * BN;
    const int tid = threadIdx.x;
    const int tx = tid & 15, ty = tid >> 4;

    const float* xg = x  + (size_t)bi * DFULL + (size_t)h * DHEAD;       // row stride DFULL
    const float* eg = cb + ((size_t)h * KCODES + kj) * DHEAD;            // row stride DHEAD

    const int lrow = tid >> 1;        // 0..127
    const int lcol = (tid & 1) * 4;   // 0 or 4

    float acc[TM][TN];
#pragma unroll
    for (int m = 0; m < TM; m++)
#pragma unroll
        for (int n = 0; n < TN; n++) acc[m][n] = 0.f;

    for (int kk = 0; kk < DHEAD; kk += BK) {
        float4 xv = *(const float4*)(xg + (size_t)lrow * DFULL + kk + lcol);
        float4 ev = *(const float4*)(eg + (size_t)lrow * DHEAD + kk + lcol);

        Xs[lcol + 0][lrow] = xv.x; Xs[lcol + 1][lrow] = xv.y;
        Xs[lcol + 2][lrow] = xv.z; Xs[lcol + 3][lrow] = xv.w;
        Es[lcol + 0][lrow] = ev.x; Es[lcol + 1][lrow] = ev.y;
        Es[lcol + 2][lrow] = ev.z; Es[lcol + 3][lrow] = ev.w;
        __syncthreads();

#pragma unroll
        for (int c = 0; c < BK; c++) {
            float rm[TM], rn[TN];
            *(float4*)&rm[0] = *(const float4*)&Xs[c][ty * TM];
            *(float4*)&rm[4] = *(const float4*)&Xs[c][ty * TM + 4];
            *(float4*)&rn[0] = *(const float4*)&Es[c][tx * TN];
            *(float4*)&rn[4] = *(const float4*)&Es[c][tx * TN + 4];
#pragma unroll
            for (int m = 0; m < TM; m++)
#pragma unroll
                for (int n = 0; n < TN; n++)
                    acc[m][n] = fmaf(rm[m], rn[n], acc[m][n]);
        }
        __syncthreads();
    }

    // Epilogue: per-row min of packed (e2 - 2*xe, code)
    float e2c[TN];
#pragma unroll
    for (int n = 0; n < TN; n++)
        e2c[n] = g_e2[h * KCODES + kj + tx * TN + n];

#pragma unroll
    for (int m = 0; m < TM; m++) {
        unsigned long long best = 0xFFFFFFFFFFFFFFFFull;
#pragma unroll
        for (int n = 0; n < TN; n++) {
            float mv = fmaf(-2.f, acc[m][n], e2c[n]);
            unsigned long long key =
                ((unsigned long long)float_key(mv) << 32) |
                (unsigned)(kj + tx * TN + n);
            best = (key < best) ? key : best;
        }
        red[ty * TM + m][tx] = best;
    }
    __syncthreads();

    if (tid < BM) {
        unsigned long long best = red[tid][0];
#pragma unroll
        for (int i = 1; i < 16; i++) {
            unsigned long long v = red[tid][i];
            best = (v < best) ? v : best;
        }
        atomicMin(&g_min[(size_t)(bi + tid) * H + h], best);
    }
}

// ---------------------------------------------------------------------------
// Finalize: gather q, write quantized/codes, loss = 0.25 * sum_h mean((q-x)^2)
// ---------------------------------------------------------------------------
__global__ void finalize_kernel(const float* __restrict__ x, const float* __restrict__ cb,
                                float* __restrict__ loss, float* __restrict__ quant,
                                float* __restrict__ codes_out) {
    const int b = blockIdx.x;
    const int tid = threadIdx.x;  // 256 threads, one per head-dim element
    __shared__ float sred[256];

    float partial = 0.f;
#pragma unroll
    for (int h = 0; h < H; h++) {
        unsigned long long packed = g_min[(size_t)b * H + h];
        unsigned code = (unsigned)(packed & 0xFFFFFFFFu);
        if (tid == 0) codes_out[(size_t)b * H + h] = (float)code;
        float qv = cb[((size_t)h * KCODES + code) * DHEAD + tid];
        float xv = x[(size_t)b * DFULL + (size_t)h * DHEAD + tid];
        quant[(size_t)b * DFULL + (size_t)h * DHEAD + tid] = qv;
        float d = qv - xv;
        partial = fmaf(d, d, partial);
    }
    sred[tid] = partial;
    __syncthreads();
#pragma unroll
    for (int s = 128; s > 0; s >>= 1) {
        if (tid < s) sred[tid] += sred[tid + s];
        __syncthreads();
    }
    if (tid == 0) loss[b] = 0.25f * sred[0] * (1.0f / (float)DHEAD);
}

// ---------------------------------------------------------------------------
extern "C" void kernel_launch(void* const* d_in, const int* in_sizes, int n_in,
                              void* d_out, int out_size) {
    const float* x  = (const float*)d_in[0];   // inputs   (B,1,D)
    const float* cb = (const float*)d_in[1];   // codebooks (H,K,d)
    float* out = (float*)d_out;

    float* loss  = out;
    float* quant = out + BATCH;
    float* codes = out + BATCH + (size_t)BATCH * DFULL;

    reset_kernel<<<(BATCH * H + 255) / 256, 256>>>();
    e2_kernel<<<(H * KCODES) / 8, 256>>>(cb);

    dim3 grid(BATCH / BM, KCODES / BN, H);
    dist_argmin_kernel<<<grid, 256>>>(x, cb);

    finalize_kernel<<<BATCH, 256>>>(x, cb, loss, quant, codes);
}